// round 2
// baseline (speedup 1.0000x reference)
#include <cuda_runtime.h>
#include <stdint.h>

// Row layout: segments (u,v) = (128,1),(64,3),(32,5),(16,7)
// out[off + a*u + b] = in[off + b*v + a]
// For output column c: a = (c-off) >> log2(u), b = (c-off) & (u-1); src = off + b*v + a

#define ROW_DIM 592
#define RPB 8                         // rows per tile
#define TILE_FLOATS (ROW_DIM * RPB)   // 4736
#define TILE_BYTES  (TILE_FLOATS * 4) // 18944 (16B multiple)
#define NT 256
#define NGROUPS (ROW_DIM / 4)         // 148 float4 groups per row
#define ITEMS (NGROUPS * RPB)         // 1184 float4 stores per tile

__device__ __forceinline__ int perm_src(int c) {
    if (c < 128) return c;
    if (c < 320) { int l = c - 128; return 128 + (l & 63) * 3 + (l >> 6); }
    if (c < 480) { int l = c - 320; return 320 + (l & 31) * 5 + (l >> 5); }
    { int l = c - 480; return 480 + (l & 15) * 7 + (l >> 4); }
}

__device__ __forceinline__ unsigned smem_u32(const void* p) {
    return (unsigned)__cvta_generic_to_shared(p);
}

__device__ __forceinline__ void mbar_init(unsigned mbar, unsigned count) {
    asm volatile("mbarrier.init.shared.b64 [%0], %1;" :: "r"(mbar), "r"(count) : "memory");
}

__device__ __forceinline__ void mbar_expect_tx(unsigned mbar, unsigned bytes) {
    asm volatile("mbarrier.arrive.expect_tx.shared.b64 _, [%0], %1;"
                 :: "r"(mbar), "r"(bytes) : "memory");
}

__device__ __forceinline__ void bulk_load(unsigned dst_smem, const void* src_gmem,
                                          unsigned bytes, unsigned mbar) {
    asm volatile("cp.async.bulk.shared::cta.global.mbarrier::complete_tx::bytes "
                 "[%0], [%1], %2, [%3];"
                 :: "r"(dst_smem), "l"(src_gmem), "r"(bytes), "r"(mbar) : "memory");
}

__device__ __forceinline__ void mbar_wait(unsigned mbar, unsigned parity) {
    asm volatile(
        "{\n\t"
        ".reg .pred P;\n\t"
        "WAIT_LOOP_%=:\n\t"
        "mbarrier.try_wait.parity.acquire.cta.shared::cta.b64 P, [%0], %1, 0x989680;\n\t"
        "@P bra.uni WAIT_DONE_%=;\n\t"
        "bra.uni WAIT_LOOP_%=;\n\t"
        "WAIT_DONE_%=:\n\t"
        "}"
        :: "r"(mbar), "r"(parity) : "memory");
}

__global__ __launch_bounds__(NT, 4)
void transpose_irreps_pipe(const float* __restrict__ in, float* __restrict__ out, int n_tiles) {
    __shared__ __align__(16) float buf[2][TILE_FLOATS];
    __shared__ __align__(8) unsigned long long mbar_s[2];
    __shared__ int4 ptab[NGROUPS];

    const int tid = threadIdx.x;

    // Precompute permutation table (float4 groups of source indices)
    for (int g = tid; g < NGROUPS; g += NT) {
        int c = 4 * g;
        ptab[g] = make_int4(perm_src(c), perm_src(c + 1), perm_src(c + 2), perm_src(c + 3));
    }

    const unsigned mb0 = smem_u32(&mbar_s[0]);
    const unsigned mb1 = smem_u32(&mbar_s[1]);
    if (tid == 0) {
        mbar_init(mb0, 1);
        mbar_init(mb1, 1);
    }
    __syncthreads();

    const long long stride = gridDim.x;
    const long long t0 = blockIdx.x;
    unsigned phase0 = 0, phase1 = 0;

    // Prologue: issue load of first tile into buf 0
    if (t0 < n_tiles && tid == 0) {
        mbar_expect_tx(mb0, TILE_BYTES);
        bulk_load(smem_u32(&buf[0][0]), in + t0 * TILE_FLOATS, TILE_BYTES, mb0);
    }

    int bi = 0;
    for (long long t = t0; t < n_tiles; t += stride) {
        // Issue load of next tile into the other buffer (safe: previous
        // iteration's __syncthreads guarantees all reads from it are done)
        long long tn = t + stride;
        if (tn < n_tiles && tid == 0) {
            int nb = bi ^ 1;
            unsigned mb = nb ? mb1 : mb0;
            mbar_expect_tx(mb, TILE_BYTES);
            bulk_load(smem_u32(&buf[nb][0]), in + tn * TILE_FLOATS, TILE_BYTES, mb);
        }

        // Wait for current tile's data
        if (bi == 0) { mbar_wait(mb0, phase0); phase0 ^= 1; }
        else         { mbar_wait(mb1, phase1); phase1 ^= 1; }

        // Permuted, vectorized, coalesced stores
        float* __restrict__ ob = out + t * TILE_FLOATS;
        const float* __restrict__ bb = &buf[bi][0];
        #pragma unroll
        for (int i = tid; i < ITEMS; i += NT) {
            int r = i / NGROUPS;          // constant-divide -> mul/shift
            int g = i - r * NGROUPS;
            int4 s = ptab[g];
            const float* sb = bb + r * ROW_DIM;
            float4 v;
            v.x = sb[s.x]; v.y = sb[s.y]; v.z = sb[s.z]; v.w = sb[s.w];
            *reinterpret_cast<float4*>(ob + r * ROW_DIM + 4 * g) = v;
        }

        __syncthreads();  // all reads of buf[bi] complete before it is refilled
        bi ^= 1;
    }
}

extern "C" void kernel_launch(void* const* d_in, const int* in_sizes, int n_in,
                              void* d_out, int out_size) {
    const float* x = (const float*)d_in[0];
    float* out = (float*)d_out;
    int n_rows = in_sizes[0] / ROW_DIM;     // 200000
    int n_tiles = n_rows / RPB;             // 25000 (exact)
    int grid = 148 * 4;                     // persistent: 4 CTAs per SM
    if (grid > n_tiles) grid = n_tiles;
    transpose_irreps_pipe<<<grid, NT>>>(x, out, n_tiles);
}